// round 11
// baseline (speedup 1.0000x reference)
#include <cuda_runtime.h>
#include <math.h>

#define B 16
#define T (1 << 20)
#define NTH 256
#define SUB 256                    // elems per k_wav warp sub-chunk
#define S128 (T / 128)             // 8192 offset slots per row (128-elem granularity)
#define WCH 2048                   // elems per k_wav block (8 warps)
#define NCH (T / WCH)              // 512 k_wav blocks per row
#define CHUNK1 8192                // elems per pass-1 block (2048 float4)
#define BPR (T / CHUNK1)           // 128 pass-1 blocks per row
#define STEP (1.0f / 48000.0f)
#define RISE_RATIO 0.66f
#define EPSV 1e-6f
#define PI_F 3.14159265358979f
#define FULL 0xFFFFFFFFu

// scratch (no device-side allocation allowed)
__device__ float  g_partials[B * S128];  // per-128-elem sum of f0*STEP
__device__ double g_offsets[B * S128];   // ps[b] + exclusive prefix, 128-granularity
__device__ int    g_count[B];            // per-row completion counters (self-resetting)

struct F8 { float v[8]; };

__device__ __forceinline__ F8 ld8(const float* p) {   // default cache policy
    unsigned r0,r1,r2,r3,r4,r5,r6,r7;
    asm("ld.global.v8.b32 {%0,%1,%2,%3,%4,%5,%6,%7}, [%8];"
        : "=r"(r0),"=r"(r1),"=r"(r2),"=r"(r3),"=r"(r4),"=r"(r5),"=r"(r6),"=r"(r7)
        : "l"(p));
    F8 f;
    f.v[0]=__uint_as_float(r0); f.v[1]=__uint_as_float(r1);
    f.v[2]=__uint_as_float(r2); f.v[3]=__uint_as_float(r3);
    f.v[4]=__uint_as_float(r4); f.v[5]=__uint_as_float(r5);
    f.v[6]=__uint_as_float(r6); f.v[7]=__uint_as_float(r7);
    return f;
}
__device__ __forceinline__ F8 ld8_ef(const float* p) {  // L2 evict-first (streaming)
    unsigned r0,r1,r2,r3,r4,r5,r6,r7;
    asm("ld.global.L2::evict_first.v8.b32 {%0,%1,%2,%3,%4,%5,%6,%7}, [%8];"
        : "=r"(r0),"=r"(r1),"=r"(r2),"=r"(r3),"=r"(r4),"=r"(r5),"=r"(r6),"=r"(r7)
        : "l"(p));
    F8 f;
    f.v[0]=__uint_as_float(r0); f.v[1]=__uint_as_float(r1);
    f.v[2]=__uint_as_float(r2); f.v[3]=__uint_as_float(r3);
    f.v[4]=__uint_as_float(r4); f.v[5]=__uint_as_float(r5);
    f.v[6]=__uint_as_float(r6); f.v[7]=__uint_as_float(r7);
    return f;
}
__device__ __forceinline__ void st8_ef(float* p, const float* w) {
    asm volatile("st.global.L2::evict_first.v8.b32 [%0], {%1,%2,%3,%4,%5,%6,%7,%8};"
        :: "l"(p),
           "r"(__float_as_uint(w[0])), "r"(__float_as_uint(w[1])),
           "r"(__float_as_uint(w[2])), "r"(__float_as_uint(w[3])),
           "r"(__float_as_uint(w[4])), "r"(__float_as_uint(w[5])),
           "r"(__float_as_uint(w[6])), "r"(__float_as_uint(w[7])) : "memory");
}

// ------- Pass 1: per-128-elem sums + fused low-reg fp64 row-scan tail --------
// Interleaved layout (fast): load slot s -> block reads 4KB contiguous.
// Warp w at slot s covers the 128-elem piece index s*8 + w within the block.
__global__ __launch_bounds__(NTH) void k_partials(const float* __restrict__ f0,
                                                  const float* __restrict__ ps,
                                                  float* __restrict__ out,
                                                  int out_size) {
    const int b = blockIdx.y, cg = blockIdx.x;
    const int t = threadIdx.x;
    const int lane = t & 31, wid = t >> 5;

    {
        const float4* p4 = reinterpret_cast<const float4*>(f0 + (size_t)b * T
                            + (size_t)cg * CHUNK1);
        float4 v[8];
#pragma unroll
        for (int s = 0; s < 8; s++)
            v[s] = p4[s * 256 + t];              // 4KB block-contiguous per load
        float r[8];
#pragma unroll
        for (int s = 0; s < 8; s++)
            r[s] = (v[s].x + v[s].y) + (v[s].z + v[s].w);
#pragma unroll
        for (int d = 16; d; d >>= 1) {
#pragma unroll
            for (int s = 0; s < 8; s++) r[s] += __shfl_down_sync(FULL, r[s], d);
        }
        if (lane == 0) {
            const int pbase = b * S128 + cg * 64 + wid;
#pragma unroll
            for (int s = 0; s < 8; s++)
                g_partials[pbase + s * 8] = r[s] * STEP;
        }
    }

    // ---- last block of this row: fp64 scan of 8192 sub-sums (low-reg) ----
    __shared__ int s_last;
    __syncthreads();
    if (t == 0) {
        __threadfence();
        s_last = (atomicAdd(&g_count[b], 1) == BPR - 1);
    }
    __syncthreads();
    if (!s_last) return;
    __threadfence();

    // Phase A: thread total of its 32 sums (no prefix array kept)
    const float4* pr = reinterpret_cast<const float4*>(g_partials + b * S128) + t * 8;
    float acc = 0.f;
#pragma unroll
    for (int i = 0; i < 8; i++) {
        float4 x = pr[i];
        acc += (x.x + x.y) + (x.z + x.w);
    }
    const double tot = (double)acc;

    double incl = tot;
#pragma unroll
    for (int d = 1; d < 32; d <<= 1) {
        double n = __shfl_up_sync(FULL, incl, d);
        if (lane >= d) incl += n;
    }
    __shared__ double dwsum[NTH / 32];
    __shared__ double dwbase[NTH / 32];
    if (lane == 31) dwsum[wid] = incl;
    __syncthreads();
    if (t == 0) {
        double r = 0.0;
#pragma unroll
        for (int i = 0; i < NTH / 32; i++) { dwbase[i] = r; r += dwsum[i]; }
        g_count[b] = 0;                           // reset for next graph replay
    }
    __syncthreads();

    // Phase B: re-read the 32 sums (cache-hot), emit offsets with running acc
    double run = (double)ps[b] + dwbase[wid] + (incl - tot);
    double* po = g_offsets + b * S128 + t * 32;
#pragma unroll
    for (int i = 0; i < 8; i++) {
        float4 x = pr[i];
        po[i * 4 + 0] = run; run += (double)x.x;
        po[i * 4 + 1] = run; run += (double)x.y;
        po[i * 4 + 2] = run; run += (double)x.z;
        po[i * 4 + 3] = run; run += (double)x.w;
    }

    if (t == NTH - 1) {                           // next_state (unwrapped)
        const long long oi = (long long)B * T + b;
        if (oi < (long long)out_size) out[oi] = (float)run;
    }
}

// ------- Pass 2: per-warp scan + Rosenberg pulse (no barriers) ---------------
__global__ __launch_bounds__(NTH) void k_wav(const float* __restrict__ f0,
                                             const float* __restrict__ oq,
                                             float* __restrict__ out) {
    const int b = blockIdx.y, ch = blockIdx.x;
    const int lane = threadIdx.x & 31, wid = threadIdx.x >> 5;
    const int sub = ch * 8 + wid;                 // this warp's 256-elem sub-chunk
    const size_t base = (size_t)b * T + (size_t)sub * SUB;

    // thread owns 8 contiguous elems
    const F8 f = ld8(f0 + base + lane * 8);       // default: L2-resident from pass 1
    const F8 q = ld8_ef(oq + base + lane * 8);    // streaming

    // thread-local inclusive prefix of 8 (STEP folded in)
    float pr[8];
    float r = f.v[0] * STEP;          pr[0] = r;
#pragma unroll
    for (int i = 1; i < 8; i++) { r = fmaf(f.v[i], STEP, r); pr[i] = r; }
    const float tot = r;

    // single warp scan of thread totals
    float incl = tot;
#pragma unroll
    for (int d = 1; d < 32; d <<= 1) {
        float n = __shfl_up_sync(FULL, incl, d);
        if (lane >= d) incl += n;
    }
    const float excl = incl - tot;

    // absolute phase base (fp64 once per warp's sub-chunk; 128-gran offsets)
    const double based = g_offsets[b * S128 + sub * 2];
    const float frac = (float)(based - floor(based));     // in [0, 1]
    const float baseph = frac + excl;

    float w[8];
#pragma unroll
    for (int j = 0; j < 8; j++) {
        float ph = baseph + pr[j];
        // ph < 1.011 provably (frac<=1, warp-local sums < 0.011): cheap wrap
        ph -= (ph >= 1.f) ? 1.f : 0.f;
        const float oqv = q.v[j];
        const float tp = oqv * RISE_RATIO;
        const float tn = oqv - tp;
        const bool rise = ph < tp;
        const bool open = ph < oqv;
        const float num = rise ? ph : ph - tp;
        const float den = rise ? tp + EPSV : fmaf(2.f, tn, EPSV);
        const float c = __cosf(PI_F * __fdividef(num, den));
        const float res = rise ? fmaf(-0.5f, c, 0.5f) : c;
        w[j] = open ? res : 0.f;
    }

    st8_ef(out + base + lane * 8, w);             // streaming store

}

extern "C" void kernel_launch(void* const* d_in, const int* in_sizes, int n_in,
                              void* d_out, int out_size) {
    const float* f0 = (const float*)d_in[0];
    const float* oq = (const float*)d_in[1];
    const float* ps = (const float*)d_in[2];
    float* out = (float*)d_out;

    dim3 grid1(BPR, B);
    k_partials<<<grid1, NTH>>>(f0, ps, out, out_size);
    dim3 grid3(NCH, B);
    k_wav<<<grid3, NTH>>>(f0, oq, out);
}

// round 12
// speedup vs baseline: 1.5565x; 1.5565x over previous
#include <cuda_runtime.h>
#include <math.h>

#define B 16
#define T (1 << 20)
#define NTH 256
#define PER 8
#define CHUNK (NTH * PER)         // 2048 elems per k_wav block / offset granule
#define NCH (T / CHUNK)           // 512 chunks per row
#define CPB 8                     // chunks per pass-1 block
#define CHUNK1 (CHUNK * CPB)      // 16384 elems per pass-1 block
#define BPR (NCH / CPB)           // 64 pass-1 blocks per row
#define STEP (1.0f / 48000.0f)
#define RISE_RATIO 0.66f
#define EPSV 1e-6f
#define PI_F 3.14159265358979f
#define FULL 0xFFFFFFFFu

// scratch (no device-side allocation allowed)
__device__ float  g_partials[B * NCH];   // per-2048-elem sum of f0*STEP
__device__ double g_offsets[B * NCH];    // ps[b] + exclusive prefix across chunks
__device__ int    g_count[B];            // per-row completion counters (self-resetting)

struct F8 { float v[8]; };

__device__ __forceinline__ F8 ld8(const float* p) {   // default cache policy
    unsigned r0,r1,r2,r3,r4,r5,r6,r7;
    asm("ld.global.v8.b32 {%0,%1,%2,%3,%4,%5,%6,%7}, [%8];"
        : "=r"(r0),"=r"(r1),"=r"(r2),"=r"(r3),"=r"(r4),"=r"(r5),"=r"(r6),"=r"(r7)
        : "l"(p));
    F8 f;
    f.v[0]=__uint_as_float(r0); f.v[1]=__uint_as_float(r1);
    f.v[2]=__uint_as_float(r2); f.v[3]=__uint_as_float(r3);
    f.v[4]=__uint_as_float(r4); f.v[5]=__uint_as_float(r5);
    f.v[6]=__uint_as_float(r6); f.v[7]=__uint_as_float(r7);
    return f;
}
__device__ __forceinline__ F8 ld8_ef(const float* p) {  // L2 evict-first (streaming)
    unsigned r0,r1,r2,r3,r4,r5,r6,r7;
    asm("ld.global.L2::evict_first.v8.b32 {%0,%1,%2,%3,%4,%5,%6,%7}, [%8];"
        : "=r"(r0),"=r"(r1),"=r"(r2),"=r"(r3),"=r"(r4),"=r"(r5),"=r"(r6),"=r"(r7)
        : "l"(p));
    F8 f;
    f.v[0]=__uint_as_float(r0); f.v[1]=__uint_as_float(r1);
    f.v[2]=__uint_as_float(r2); f.v[3]=__uint_as_float(r3);
    f.v[4]=__uint_as_float(r4); f.v[5]=__uint_as_float(r5);
    f.v[6]=__uint_as_float(r6); f.v[7]=__uint_as_float(r7);
    return f;
}
__device__ __forceinline__ void st8_ef(float* p, const float* w) {
    asm volatile("st.global.L2::evict_first.v8.b32 [%0], {%1,%2,%3,%4,%5,%6,%7,%8};"
        :: "l"(p),
           "r"(__float_as_uint(w[0])), "r"(__float_as_uint(w[1])),
           "r"(__float_as_uint(w[2])), "r"(__float_as_uint(w[3])),
           "r"(__float_as_uint(w[4])), "r"(__float_as_uint(w[5])),
           "r"(__float_as_uint(w[6])), "r"(__float_as_uint(w[7])) : "memory");
}

// ------- Pass 1 (VERBATIM Round-5, measured 12.4us incl fused fp64 scan) -----
__global__ __launch_bounds__(NTH) void k_partials(const float* __restrict__ f0,
                                                  const float* __restrict__ ps,
                                                  float* __restrict__ out,
                                                  int out_size) {
    const int b = blockIdx.y, cg = blockIdx.x;
    const float4* p = reinterpret_cast<const float4*>(f0 + (size_t)b * T + (size_t)cg * CHUNK1);
    const int t = threadIdx.x;
    const int lane = t & 31, wid = t >> 5;

    float s[CPB];
    {
        float4 v[CPB];
#pragma unroll
        for (int c = 0; c < CPB; c++) v[c] = p[c * 512 + t];
#pragma unroll
        for (int c = 0; c < CPB; c++)
            s[c] = (v[c].x + v[c].y) + (v[c].z + v[c].w);
#pragma unroll
        for (int c = 0; c < CPB; c++) v[c] = p[c * 512 + 256 + t];
#pragma unroll
        for (int c = 0; c < CPB; c++)
            s[c] += (v[c].x + v[c].y) + (v[c].z + v[c].w);
    }

#pragma unroll
    for (int d = 16; d; d >>= 1) {
#pragma unroll
        for (int c = 0; c < CPB; c++) s[c] += __shfl_down_sync(FULL, s[c], d);
    }
    __shared__ float ws[CPB][NTH / 32];
    if (lane == 0) {
#pragma unroll
        for (int c = 0; c < CPB; c++) ws[c][wid] = s[c];
    }
    __syncthreads();
    if (t < CPB) {
        float r = 0.f;
#pragma unroll
        for (int i = 0; i < NTH / 32; i++) r += ws[t][i];
        g_partials[b * NCH + cg * CPB + t] = r * STEP;
    }

    // ---- last block of this row performs the fp64 row scan ----
    __shared__ int s_last;
    __syncthreads();
    if (t == 0) {
        __threadfence();
        s_last = (atomicAdd(&g_count[b], 1) == BPR - 1);
    }
    __syncthreads();
    if (!s_last) return;
    __threadfence();

    // 256 threads, 2 chunks each: scan 512 chunk sums in double
    const float* pr = g_partials + b * NCH;
    const double v0 = (double)pr[2 * t];
    const double v1 = (double)pr[2 * t + 1];
    const double pair = v0 + v1;

    double incl = pair;
#pragma unroll
    for (int d = 1; d < 32; d <<= 1) {
        double n = __shfl_up_sync(FULL, incl, d);
        if (lane >= d) incl += n;
    }
    __shared__ double dwsum[NTH / 32];
    __shared__ double dwbase[NTH / 32];
    if (lane == 31) dwsum[wid] = incl;
    __syncthreads();
    if (t == 0) {
        double r = 0.0;
#pragma unroll
        for (int i = 0; i < NTH / 32; i++) { dwbase[i] = r; r += dwsum[i]; }
        g_count[b] = 0;                               // reset for next graph replay
    }
    __syncthreads();

    const double excl = (double)ps[b] + dwbase[wid] + (incl - pair);
    g_offsets[b * NCH + 2 * t]     = excl;
    g_offsets[b * NCH + 2 * t + 1] = excl + v0;

    if (t == NTH - 1) {                               // next_state (unwrapped)
        const long long oi = (long long)B * T + b;
        if (oi < (long long)out_size) out[oi] = (float)(excl + pair);
    }
}

// ------- Pass 2: thread-owns-8, warp scan + 8-entry smem scan, 1 divide ------
__global__ __launch_bounds__(NTH) void k_wav(const float* __restrict__ f0,
                                             const float* __restrict__ oq,
                                             float* __restrict__ out) {
    const int b = blockIdx.y, ch = blockIdx.x;
    const int t = threadIdx.x;
    const int lane = t & 31, wid = t >> 5;
    const size_t base = (size_t)b * T + (size_t)ch * CHUNK;

    // thread owns 8 contiguous elems
    const F8 f = ld8(f0 + base + t * 8);          // default: may hit L2 from pass 1
    const F8 q = ld8_ef(oq + base + t * 8);       // streaming

    // thread-local inclusive prefix of 8 (STEP folded in)
    float pr[8];
    float r = f.v[0] * STEP;          pr[0] = r;
#pragma unroll
    for (int i = 1; i < 8; i++) { r = fmaf(f.v[i], STEP, r); pr[i] = r; }
    const float tot = r;

    // warp scan of thread totals
    float incl = tot;
#pragma unroll
    for (int d = 1; d < 32; d <<= 1) {
        float n = __shfl_up_sync(FULL, incl, d);
        if (lane >= d) incl += n;
    }
    const float excl = incl - tot;

    // cross-warp exclusive scan (8 warps)
    __shared__ float wsum[NTH / 32];
    __shared__ float wbase[NTH / 32];
    if (lane == 31) wsum[wid] = incl;
    __syncthreads();
    if (t == 0) {
        float a = 0.f;
#pragma unroll
        for (int i = 0; i < NTH / 32; i++) { wbase[i] = a; a += wsum[i]; }
    }
    __syncthreads();

    // absolute phase base (fp64 once per thread; 2048-gran offsets)
    const double based = g_offsets[b * NCH + ch];
    const float frac = (float)(based - floor(based));     // in [0, 1]
    const float baseph = frac + wbase[wid] + excl;        // < 1 + 2048/48000 ~ 1.043

    float w[8];
#pragma unroll
    for (int j = 0; j < 8; j++) {
        float ph = baseph + pr[j];
        ph -= (ph >= 1.f) ? 1.f : 0.f;            // cheap wrap (ph < 1.05 provable)
        const float oqv = q.v[j];
        const float tp = oqv * RISE_RATIO;
        const float tn = oqv - tp;
        const bool rise = ph < tp;
        const bool open = ph < oqv;
        const float num = rise ? ph : ph - tp;
        const float den = rise ? tp + EPSV : fmaf(2.f, tn, EPSV);
        const float c = __cosf(PI_F * __fdividef(num, den));
        const float res = rise ? fmaf(-0.5f, c, 0.5f) : c;
        w[j] = open ? res : 0.f;
    }

    st8_ef(out + base + t * 8, w);                // streaming store
}

extern "C" void kernel_launch(void* const* d_in, const int* in_sizes, int n_in,
                              void* d_out, int out_size) {
    const float* f0 = (const float*)d_in[0];
    const float* oq = (const float*)d_in[1];
    const float* ps = (const float*)d_in[2];
    float* out = (float*)d_out;

    dim3 grid1(BPR, B);
    k_partials<<<grid1, NTH>>>(f0, ps, out, out_size);
    dim3 grid3(NCH, B);
    k_wav<<<grid3, NTH>>>(f0, oq, out);
}